// round 1
// baseline (speedup 1.0000x reference)
#include <cuda_runtime.h>
#include <math.h>

// Problem constants (from reference)
#define AEMB   16      // A
#define DIN    480     // node_vec row length
#define OUT0D  224     // W1_l0 last-dim stride (we only use k < 128)
#define M0     128     // MUL0 = live output channels of layer 1
#define BM     128     // nodes per CTA
#define NTH    256

// Shared memory layout (floats)
#define X0_PITCH 129                       // pad to kill bank conflicts
#define AS_OFF   (BM * X0_PITCH)           // 16512
#define WB_OFF   (AS_OFF + BM * AEMB)      // +2048 = 18560
#define MID_OFF  (WB_OFF + 4096)           // double-buffered 2*16*128 W chunk
#define SMEM_FLOATS (MID_OFF + BM * AEMB)  // 24704 floats
#define SMEM_BYTES (SMEM_FLOATS * 4)       // 98816 bytes

// ---- packed f32x2 helpers (ptxas will not auto-fuse; PTX-only path) ----
__device__ __forceinline__ unsigned long long pk2(float lo, float hi) {
    unsigned long long d;
    asm("mov.b64 %0, {%1, %2};" : "=l"(d) : "f"(lo), "f"(hi));
    return d;
}
__device__ __forceinline__ unsigned long long fma2(unsigned long long a,
                                                   unsigned long long b,
                                                   unsigned long long c) {
    unsigned long long d;
    asm("fma.rn.f32x2 %0, %1, %2, %3;" : "=l"(d) : "l"(a), "l"(b), "l"(c));
    return d;
}
__device__ __forceinline__ void upk2(unsigned long long v, float& lo, float& hi) {
    asm("mov.b64 {%0, %1}, %2;" : "=f"(lo), "=f"(hi) : "l"(v));
}

__device__ __forceinline__ float silu_f(float x) {
    return x / (1.0f + __expf(-x));
}

__global__ void __launch_bounds__(NTH, 1)
tp_head_kernel(const float* __restrict__ nv,   // node_vec   [N,480]
               const float* __restrict__ ae,   // embedding  [N,16]
               const float* __restrict__ W1,   // W1_l0      [128,16,224]
               const float* __restrict__ b1,   // [224]
               const float* __restrict__ W2,   // [128,16,16]
               const float* __restrict__ b2,   // [16]
               const float* __restrict__ W3,   // [16,16]
               const float* __restrict__ b3,   // [16]
               const float* __restrict__ W4,   // [16,1]
               const float* __restrict__ b4,   // [1]
               float* __restrict__ out)        // [N]
{
    extern __shared__ float sm[];
    float* x0s  = sm;             // [128][129]  x0 tile, later reused for scalars
    float* as_  = sm + AS_OFF;    // [128][16]   embedding tile
    float* wb   = sm + WB_OFF;    // [2][16][128] W1 chunk double buffer / W2 chunk
    float* mids = sm + MID_OFF;   // [128][16]

    const int tid = threadIdx.x;
    const int n0  = blockIdx.x * BM;

    // ---- Phase 0: stage x0 tile (first 128 cols of node_vec) and a tile ----
    for (int t = tid; t < BM * 32; t += NTH) {           // 32 float4 per row
        int lr = t >> 5, c4 = (t & 31) << 2;
        float4 v = *(const float4*)(nv + (size_t)(n0 + lr) * DIN + c4);
        float* dst = x0s + lr * X0_PITCH + c4;           // pitch 129: scalar stores
        dst[0] = v.x; dst[1] = v.y; dst[2] = v.z; dst[3] = v.w;
    }
    for (int t = tid; t < BM * 4; t += NTH) {            // 4 float4 per row
        int lr = t >> 2, c4 = (t & 3) << 2;
        *(float4*)(as_ + lr * AEMB + c4) =
            *(const float4*)(ae + (size_t)(n0 + lr) * AEMB + c4);
    }
    // preload W1 chunk for i = 0  (rows a=0..15, k=0..127)
    for (int t = tid; t < 512; t += NTH) {
        int row = t >> 5, c4 = (t & 31) << 2;
        *(float4*)(wb + row * M0 + c4) =
            *(const float4*)(W1 + (size_t)row * OUT0D + c4);
    }
    __syncthreads();

    // ---- Phase 1: s[n,k] = sum_{i,a} x0[n,i] a[n,a] W1[i,a,k],  k < 128 ----
    const int tx = tid & 15;          // k group: k = tx*8 + c
    const int ty = tid >> 4;          // node group: n = ty + 16*r
    unsigned long long acc[8][4];
#pragma unroll
    for (int r = 0; r < 8; ++r)
#pragma unroll
        for (int q = 0; q < 4; ++q) acc[r][q] = 0ULL;

    for (int i = 0; i < M0; ++i) {
        const float* wcur  = wb + ((i & 1) << 11);
        float*       wnext = wb + (((i + 1) & 1) << 11);
        if (i + 1 < M0) {             // prefetch next 16x128 W chunk
            const float* src = W1 + (size_t)(i + 1) * 16 * OUT0D;
            for (int t = tid; t < 512; t += NTH) {
                int row = t >> 5, c4 = (t & 31) << 2;
                *(float4*)(wnext + row * M0 + c4) =
                    *(const float4*)(src + (size_t)row * OUT0D + c4);
            }
        }
        float x0v[8];
#pragma unroll
        for (int r = 0; r < 8; ++r)
            x0v[r] = x0s[(ty + 16 * r) * X0_PITCH + i];
#pragma unroll
        for (int a = 0; a < 16; ++a) {
            unsigned long long w[4];
            const unsigned long long* wp =
                (const unsigned long long*)(wcur + a * M0 + tx * 8);
#pragma unroll
            for (int q = 0; q < 4; ++q) w[q] = wp[q];
#pragma unroll
            for (int r = 0; r < 8; ++r) {
                float z = x0v[r] * as_[(ty + 16 * r) * AEMB + a];
                unsigned long long zz = pk2(z, z);
#pragma unroll
                for (int q = 0; q < 4; ++q) acc[r][q] = fma2(zz, w[q], acc[r][q]);
            }
        }
        __syncthreads();
    }

    // ---- Epilogue 1: scalars = silu(s/sqrt(2048) + b1[k]), store into x0s ----
    const float INV = 0.022097086912079608f;   // 1/sqrt(128*16)
#pragma unroll
    for (int r = 0; r < 8; ++r) {
        int lr = ty + 16 * r;
#pragma unroll
        for (int q = 0; q < 4; ++q) {
            float lo, hi;
            upk2(acc[r][q], lo, hi);
            int k = tx * 8 + 2 * q;
            float s0 = lo * INV + b1[k];
            float s1 = hi * INV + b1[k + 1];
            x0s[lr * X0_PITCH + k]     = silu_f(s0);
            x0s[lr * X0_PITCH + k + 1] = silu_f(s1);
        }
    }
    __syncthreads();

    // ---- Phase 2: mid[n,j] = sum_{i,a} scal[n,i] a[n,a] W2[i,a,j] * INV + b2 ----
    const int nd = tid >> 1;          // node 0..127
    const int jh = tid & 1;           // j half: j = jh*8 + jj
    float areg[16];
#pragma unroll
    for (int a = 0; a < 16; ++a) areg[a] = as_[nd * AEMB + a];
    unsigned long long m2[4] = {0ULL, 0ULL, 0ULL, 0ULL};

    for (int ic = 0; ic < 8; ++ic) {  // 8 chunks of 16 i's
        __syncthreads();
        for (int t = tid; t < 1024; t += NTH) {      // 4096 floats = 16KB
            *(float4*)(wb + t * 4) =
                *(const float4*)(W2 + (size_t)ic * 4096 + t * 4);
        }
        __syncthreads();
#pragma unroll 2
        for (int ii = 0; ii < 16; ++ii) {
            float si = x0s[nd * X0_PITCH + ic * 16 + ii];
#pragma unroll
            for (int a = 0; a < 16; ++a) {
                float za = si * areg[a];
                unsigned long long zz = pk2(za, za);
                const unsigned long long* wp =
                    (const unsigned long long*)(wb + ii * 256 + a * 16 + jh * 8);
#pragma unroll
                for (int q = 0; q < 4; ++q) m2[q] = fma2(zz, wp[q], m2[q]);
            }
        }
    }
#pragma unroll
    for (int q = 0; q < 4; ++q) {
        float lo, hi;
        upk2(m2[q], lo, hi);
        int j = jh * 8 + 2 * q;
        mids[nd * AEMB + j]     = lo * INV + b2[j];
        mids[nd * AEMB + j + 1] = hi * INV + b2[j + 1];
    }
    __syncthreads();

    // ---- Phase 3: h = silu(mid @ W3 / 4 + b3); out = h @ W4 / 4 + b4 ----
    if (tid < BM) {
        float mv[16];
#pragma unroll
        for (int j = 0; j < 16; ++j) mv[j] = mids[tid * AEMB + j];
        float o = 0.0f;
#pragma unroll
        for (int jo = 0; jo < 16; ++jo) {
            float t = 0.0f;
#pragma unroll
            for (int ji = 0; ji < 16; ++ji) t += mv[ji] * W3[ji * 16 + jo];
            t = t * 0.25f + b3[jo];
            o += silu_f(t) * W4[jo];
        }
        out[n0 + tid] = o * 0.25f + b4[0];
    }
}

extern "C" void kernel_launch(void* const* d_in, const int* in_sizes, int n_in,
                              void* d_out, int out_size) {
    const float* nv = (const float*)d_in[0];   // node_vec
    const float* ae = (const float*)d_in[1];   // node_embedding
    const float* W1 = (const float*)d_in[2];   // W1_l0
    // d_in[3], d_in[4] = W1_l1, W1_l2 : dead code in the reference
    const float* b1 = (const float*)d_in[5];
    const float* W2 = (const float*)d_in[6];
    const float* b2 = (const float*)d_in[7];
    const float* W3 = (const float*)d_in[8];
    const float* b3 = (const float*)d_in[9];
    const float* W4 = (const float*)d_in[10];
    const float* b4 = (const float*)d_in[11];
    float* out = (float*)d_out;

    int nodes = in_sizes[1] / AEMB;            // N from embedding size
    int grid  = nodes / BM;

    cudaFuncSetAttribute(tp_head_kernel,
                         cudaFuncAttributeMaxDynamicSharedMemorySize, SMEM_BYTES);
    tp_head_kernel<<<grid, NTH, SMEM_BYTES>>>(nv, ae, W1, b1, W2, b2,
                                              W3, b3, W4, b4, out);
}